// round 5
// baseline (speedup 1.0000x reference)
#include <cuda_runtime.h>
#include <cuda_bf16.h>
#include <cstdint>
#include <math.h>

#define NTOK 16384
#define DIM  256
#define NEMB 16384
#define TM 128
#define TN 256
#define NSTEP 16
#define PITCH 48
#define ZH_OFF 0
#define ZL_OFF (128 * PITCH)            // 6144
#define EH_OFF (2 * 128 * PITCH)        // 12288
#define EL_OFF (EH_OFF + 256 * PITCH)   // 24576
#define STAGE_B (EL_OFF + 256 * PITCH)  // 36864
#define NSTAGE 3
#define SMEM_TOTAL (NSTAGE * STAGE_B)   // 110592

// ---- scratch (no allocations allowed) ----
__device__ float g_zf[NTOK * DIM];
__device__ __align__(16) __nv_bfloat16 g_zh[NTOK * DIM];
__device__ __align__(16) __nv_bfloat16 g_zl[NTOK * DIM];
__device__ __align__(16) __nv_bfloat16 g_eh[NEMB * DIM];
__device__ __align__(16) __nv_bfloat16 g_el[NEMB * DIM];
__device__ float g_A[NTOK];
__device__ float g_B[NEMB];
__device__ unsigned long long g_best[NTOK];
__device__ int g_cnt[NEMB];
__device__ double g_part[4096];

// ---- asm helpers ----
__device__ __forceinline__ uint32_t smem_u32(const void* p) {
    uint32_t a;
    asm("{ .reg .u64 t; cvta.to.shared.u64 t, %1; cvt.u32.u64 %0, t; }" : "=r"(a) : "l"(p));
    return a;
}
#define LDSM4(r, addr) \
    asm volatile("ldmatrix.sync.aligned.m8n8.x4.shared.b16 {%0,%1,%2,%3}, [%4];" \
        : "=r"((r)[0]), "=r"((r)[1]), "=r"((r)[2]), "=r"((r)[3]) : "r"(addr))
#define MMA_BF16(c, a, b0, b1) \
    asm volatile("mma.sync.aligned.m16n8k16.row.col.f32.bf16.bf16.f32 " \
        "{%0,%1,%2,%3}, {%4,%5,%6,%7}, {%8,%9}, {%0,%1,%2,%3};" \
        : "+f"((c)[0]), "+f"((c)[1]), "+f"((c)[2]), "+f"((c)[3]) \
        : "r"((a)[0]), "r"((a)[1]), "r"((a)[2]), "r"((a)[3]), "r"(b0), "r"(b1))
#define CP16(dst, src) \
    asm volatile("cp.async.cg.shared.global [%0], [%1], 16;" :: "r"(dst), "l"(src))
#define CP_COMMIT() asm volatile("cp.async.commit_group;" ::: "memory")
#define CP_WAIT2()  asm volatile("cp.async.wait_group 2;" ::: "memory")

// ---------------- prep kernels ----------------
__global__ void k_init() {
    int i = blockIdx.x * blockDim.x + threadIdx.x;
    if (i < NTOK) g_best[i] = 0xFFFFFFFFFFFFFFFFull;
    if (i < NEMB) g_cnt[i] = 0;
}

__global__ void k_prep_z(const float* __restrict__ z) {
    __shared__ float tile[32][33];
    int b = blockIdx.z, c0 = blockIdx.y * 32, p0 = blockIdx.x * 32;
    int tx = threadIdx.x, ty = threadIdx.y;
    tile[ty][tx] = z[((size_t)(b * 256 + c0 + ty)) * 1024 + p0 + tx];
    __syncthreads();
    float v = tile[tx][ty];
    size_t idx = ((size_t)(b * 1024 + p0 + ty)) * DIM + c0 + tx;
    g_zf[idx] = v;
    __nv_bfloat16 h = __float2bfloat16(v);
    g_zh[idx] = h;
    g_zl[idx] = __float2bfloat16(v - __bfloat162float(h));
}

__global__ void k_prep_e(const float* __restrict__ e) {
    int wid = threadIdx.x >> 5, lid = threadIdx.x & 31;
    int r = blockIdx.x * 8 + wid;
    const float* row = e + (size_t)r * DIM;
    double s = 0.0;
#pragma unroll
    for (int i = 0; i < 8; ++i) {
        int c = i * 32 + lid;
        float v = row[c];
        __nv_bfloat16 h = __float2bfloat16(v);
        g_eh[(size_t)r * DIM + c] = h;
        g_el[(size_t)r * DIM + c] = __float2bfloat16(v - __bfloat162float(h));
        s += (double)v * (double)v;
    }
#pragma unroll
    for (int o = 16; o; o >>= 1) s += __shfl_down_sync(0xffffffffu, s, o);
    if (lid == 0) g_B[r] = (float)s;
}

__global__ void k_normA() {
    int wid = threadIdx.x >> 5, lid = threadIdx.x & 31;
    int r = blockIdx.x * 8 + wid;
    const float* row = g_zf + (size_t)r * DIM;
    double s = 0.0;
#pragma unroll
    for (int i = 0; i < 8; ++i) {
        float v = row[i * 32 + lid];
        s += (double)v * (double)v;
    }
#pragma unroll
    for (int o = 16; o; o >>= 1) s += __shfl_down_sync(0xffffffffu, s, o);
    if (lid == 0) g_A[r] = (float)s;
}

// ---------------- HMMA bf16-split distance + argmin ----------------
// grid (128, 64); 256 thr; warp grid 2x4 (wr=wid&1, wc=wid>>1); warp tile 64x64.
// cp.async 3-stage pipeline, K-step 16.
__device__ __forceinline__ void stage_load(uint32_t sbase, int ks, int tid,
                                           int tok0, int cb) {
    int k0 = ks * 16;
    int zr = tid >> 1, zp = (tid & 1) * 16;
    const char* gzh = reinterpret_cast<const char*>(&g_zh[(size_t)(tok0 + zr) * DIM + k0]);
    const char* gzl = reinterpret_cast<const char*>(&g_zl[(size_t)(tok0 + zr) * DIM + k0]);
    CP16(sbase + ZH_OFF + (uint32_t)(zr * PITCH + zp), gzh + zp);
    CP16(sbase + ZL_OFF + (uint32_t)(zr * PITCH + zp), gzl + zp);
    const char* geh = reinterpret_cast<const char*>(&g_eh[(size_t)(cb + tid) * DIM + k0]);
    const char* gel = reinterpret_cast<const char*>(&g_el[(size_t)(cb + tid) * DIM + k0]);
    uint32_t er = (uint32_t)(tid * PITCH);
    CP16(sbase + EH_OFF + er, geh);
    CP16(sbase + EH_OFF + er + 16, geh + 16);
    CP16(sbase + EL_OFF + er, gel);
    CP16(sbase + EL_OFF + er + 16, gel + 16);
}

extern "C" __global__ void __launch_bounds__(256, 1)
k_argmin() {
    extern __shared__ char smem[];
    uint32_t sb = smem_u32(smem);
    int tid = threadIdx.x;
    int l = tid & 31, wid = tid >> 5;
    int wr = wid & 1, wc = wid >> 1;
    int tok0 = blockIdx.x * TM, cb = blockIdx.y * TN;

    float acc[4][8][4];
#pragma unroll
    for (int mt = 0; mt < 4; ++mt)
#pragma unroll
        for (int n2 = 0; n2 < 8; ++n2)
#pragma unroll
            for (int f = 0; f < 4; ++f) acc[mt][n2][f] = 0.0f;

    // prologue: stages 0..2
#pragma unroll
    for (int s = 0; s < NSTAGE; ++s) {
        stage_load(sb + (uint32_t)(s * STAGE_B), s, tid, tok0, cb);
        CP_COMMIT();
    }

    uint32_t a_lane = (uint32_t)((l & 15) * PITCH + (l >> 4) * 16);
    uint32_t b_lane = (uint32_t)(((l & 7) + ((l >> 4) << 3)) * PITCH + ((l >> 3) & 1) * 16);

    int buf = 0;
    for (int ks = 0; ks < NSTEP; ++ks) {
        CP_WAIT2();
        __syncthreads();
        uint32_t sbase = sb + (uint32_t)(buf * STAGE_B);

        uint32_t Bh[4][4], Bl[4][4];
#pragma unroll
        for (int nt = 0; nt < 4; ++nt) {
            uint32_t bd = sbase + EH_OFF + (uint32_t)((wc * 64 + nt * 16) * PITCH) + b_lane;
            LDSM4(Bh[nt], bd);
            LDSM4(Bl[nt], bd + (EL_OFF - EH_OFF));
        }
#pragma unroll
        for (int mt = 0; mt < 4; ++mt) {
            uint32_t Ah[4], Al[4];
            uint32_t ad = sbase + (uint32_t)((wr * 64 + mt * 16) * PITCH) + a_lane;
            LDSM4(Ah, ad);
            LDSM4(Al, ad + ZL_OFF);
#pragma unroll
            for (int nt = 0; nt < 4; ++nt)
#pragma unroll
                for (int h = 0; h < 2; ++h) {
                    float* c = acc[mt][nt * 2 + h];
                    MMA_BF16(c, Ah, Bh[nt][2 * h], Bh[nt][2 * h + 1]);   // zh*eh
                    MMA_BF16(c, Ah, Bl[nt][2 * h], Bl[nt][2 * h + 1]);   // zh*el
                    MMA_BF16(c, Al, Bh[nt][2 * h], Bh[nt][2 * h + 1]);   // zl*eh
                }
        }
        __syncthreads();
        if (ks + NSTAGE < NSTEP)
            stage_load(sb + (uint32_t)(buf * STAGE_B), ks + NSTAGE, tid, tok0, cb);
        CP_COMMIT();
        buf = (buf + 1 == NSTAGE) ? 0 : buf + 1;
    }

    // epilogue: d = fl(fl(A+B) - fl(dot+dot)), packed argmin, lowest-index tie-break
    __syncthreads();
    unsigned long long* cand = reinterpret_cast<unsigned long long*>(smem);
    if (tid < TM) cand[tid] = 0xFFFFFFFFFFFFFFFFull;
    __syncthreads();

#pragma unroll
    for (int mt = 0; mt < 4; ++mt)
#pragma unroll
        for (int fr = 0; fr < 2; ++fr) {
            int trow = wr * 64 + mt * 16 + (l >> 2) + fr * 8;
            float Aval = g_A[tok0 + trow];
            unsigned long long best = 0xFFFFFFFFFFFFFFFFull;
#pragma unroll
            for (int n2 = 0; n2 < 8; ++n2)
#pragma unroll
                for (int fc = 0; fc < 2; ++fc) {
                    int code = cb + wc * 64 + n2 * 8 + 2 * (l & 3) + fc;
                    float dot = acc[mt][n2][fr * 2 + fc];
                    float d = __fadd_rn(__fadd_rn(Aval, g_B[code]),
                                        -__fadd_rn(dot, dot));
                    unsigned long long p =
                        ((unsigned long long)__float_as_uint(d) << 32) | (unsigned)code;
                    if (p < best) best = p;
                }
            unsigned long long o;
            o = __shfl_xor_sync(0xffffffffu, best, 1); if (o < best) best = o;
            o = __shfl_xor_sync(0xffffffffu, best, 2); if (o < best) best = o;
            if ((l & 3) == 0) atomicMin(&cand[trow], best);
        }
    __syncthreads();
    if (tid < TM) atomicMin(&g_best[tok0 + tid], cand[tid]);
}

// ---------------- outputs ----------------
__global__ void k_idx(float* __restrict__ out_idx, float* __restrict__ out_enc) {
    int n = blockIdx.x * blockDim.x + threadIdx.x;
    if (n >= NTOK) return;
    int idx = (int)(g_best[n] & 0xFFFFFFFFull);
    out_idx[n] = (float)idx;
    out_enc[(size_t)n * NEMB + idx] = 1.0f;
    atomicAdd(&g_cnt[idx], 1);
}

__global__ void k_finalize(const float* __restrict__ emb, float* __restrict__ out_zq) {
    __shared__ double red[1024];
    int g = blockIdx.x * 1024 + threadIdx.x;
    int b = g >> 18, c = (g >> 10) & 255, p = g & 1023;
    int n = b * 1024 + p;
    int idx = (int)(g_best[n] & 0xFFFFFFFFull);
    float zq = emb[(size_t)idx * DIM + c];
    float zp = g_zf[(size_t)n * DIM + c];
    float diff = __fsub_rn(zq, zp);
    out_zq[g] = __fadd_rn(zp, diff);
    red[threadIdx.x] = (double)__fmul_rn(diff, diff);
    __syncthreads();
    for (int s = 512; s > 0; s >>= 1) {
        if (threadIdx.x < s) red[threadIdx.x] += red[threadIdx.x + s];
        __syncthreads();
    }
    if (threadIdx.x == 0) g_part[blockIdx.x] = red[0];
}

__global__ void k_scalars(float* __restrict__ out_loss, float* __restrict__ out_perp) {
    __shared__ double red[1024];
    int t = threadIdx.x;
    double s = 0.0;
    for (int i = t; i < 4096; i += 1024) s += g_part[i];
    red[t] = s;
    __syncthreads();
    for (int w = 512; w > 0; w >>= 1) {
        if (t < w) red[t] += red[t + w];
        __syncthreads();
    }
    double total = red[0];
    __syncthreads();
    double ent = 0.0;
    for (int j = t; j < NEMB; j += 1024) {
        double e = (double)g_cnt[j] / (double)NTOK;
        ent += e * log(e + 1e-10);
    }
    red[t] = ent;
    __syncthreads();
    for (int w = 512; w > 0; w >>= 1) {
        if (t < w) red[t] += red[t + w];
        __syncthreads();
    }
    if (t == 0) {
        double m = total / (double)(NTOK * DIM);
        *out_loss = (float)(m + 0.25 * m);
        *out_perp = (float)exp(-red[0]);
    }
}

extern "C" void kernel_launch(void* const* d_in, const int* in_sizes, int n_in,
                              void* d_out, int out_size) {
    const float* z = (const float*)d_in[0];
    const float* emb = (const float*)d_in[1];
    float* out = (float*)d_out;

    const size_t ZQ_OFF = 0;
    const size_t LOSS_OFF = 4194304;
    const size_t PERP_OFF = 4194305;
    const size_t ENC_OFF = 4194306;
    const size_t IDX_OFF = ENC_OFF + (size_t)NTOK * NEMB;

    cudaFuncSetAttribute(k_argmin, cudaFuncAttributeMaxDynamicSharedMemorySize, SMEM_TOTAL);

    cudaMemsetAsync(out + ENC_OFF, 0, (size_t)NTOK * NEMB * sizeof(float));
    k_init<<<64, 256>>>();
    {
        dim3 grid(32, 8, 16), blk(32, 32);
        k_prep_z<<<grid, blk>>>(z);
    }
    k_prep_e<<<2048, 256>>>(emb);
    k_normA<<<2048, 256>>>();
    {
        dim3 grid(NTOK / TM, NEMB / TN);
        k_argmin<<<grid, 256, SMEM_TOTAL>>>();
    }
    k_idx<<<64, 256>>>(out + IDX_OFF, out + ENC_OFF);
    k_finalize<<<4096, 1024>>>(emb, out + ZQ_OFF);
    k_scalars<<<1, 1024>>>(out + LOSS_OFF, out + PERP_OFF);
    (void)in_sizes; (void)n_in; (void)out_size;
}

// round 7
// speedup vs baseline: 2.1298x; 2.1298x over previous
#include <cuda_runtime.h>
#include <cuda_bf16.h>
#include <cuda_fp16.h>
#include <cstdint>
#include <math.h>

#define NTOK 16384
#define DIM  256
#define NEMB 16384
#define TM 128
#define TN 128
#define NSTEP 16
#define PITCH 48
#define ZH_OFF 0
#define EH_OFF (128 * PITCH)
#define STAGE_B (2 * 128 * PITCH)   // 12288
#define MARGIN 4.0e-4f
#define NCAND_CAP (1 << 21)

// ---- scratch (no allocations allowed) ----
__device__ float g_zf[NTOK * DIM];
__device__ __align__(16) __nv_bfloat16 g_zh[NTOK * DIM];
__device__ __align__(16) __nv_bfloat16 g_eh[NEMB * DIM];
__device__ __align__(16) __half g_dmat[(size_t)NTOK * NEMB];   // 512 MB
__device__ float g_A[NTOK];
__device__ float g_B[NEMB];
__device__ unsigned g_cmin[NTOK];
__device__ unsigned long long g_best[NTOK];
__device__ int g_ncand;
__device__ unsigned g_cand[NCAND_CAP];
__device__ int g_cnt[NEMB];
__device__ double g_part[4096];

// ---- asm helpers ----
__device__ __forceinline__ uint32_t smem_u32(const void* p) {
    uint32_t a;
    asm("{ .reg .u64 t; cvta.to.shared.u64 t, %1; cvt.u32.u64 %0, t; }" : "=r"(a) : "l"(p));
    return a;
}
#define LDSM4(r, addr) \
    asm volatile("ldmatrix.sync.aligned.m8n8.x4.shared.b16 {%0,%1,%2,%3}, [%4];" \
        : "=r"((r)[0]), "=r"((r)[1]), "=r"((r)[2]), "=r"((r)[3]) : "r"(addr))
#define MMA_BF16(c, a, b0, b1) \
    asm volatile("mma.sync.aligned.m16n8k16.row.col.f32.bf16.bf16.f32 " \
        "{%0,%1,%2,%3}, {%4,%5,%6,%7}, {%8,%9}, {%0,%1,%2,%3};" \
        : "+f"((c)[0]), "+f"((c)[1]), "+f"((c)[2]), "+f"((c)[3]) \
        : "r"((a)[0]), "r"((a)[1]), "r"((a)[2]), "r"((a)[3]), "r"(b0), "r"(b1))

// ---------------- prep kernels ----------------
__global__ void k_init() {
    int i = blockIdx.x * blockDim.x + threadIdx.x;
    if (i < NTOK) {
        g_best[i] = 0xFFFFFFFFFFFFFFFFull;
        g_cmin[i] = 0xFFFFFFFFu;
    }
    if (i < NEMB) g_cnt[i] = 0;
    if (i == 0) g_ncand = 0;
}

__global__ void k_prep_z(const float* __restrict__ z) {
    __shared__ float tile[32][33];
    int b = blockIdx.z, c0 = blockIdx.y * 32, p0 = blockIdx.x * 32;
    int tx = threadIdx.x, ty = threadIdx.y;
    tile[ty][tx] = z[((size_t)(b * 256 + c0 + ty)) * 1024 + p0 + tx];
    __syncthreads();
    float v = tile[tx][ty];
    size_t idx = ((size_t)(b * 1024 + p0 + ty)) * DIM + c0 + tx;
    g_zf[idx] = v;
    g_zh[idx] = __float2bfloat16(v);
}

__global__ void k_prep_e(const float* __restrict__ e) {
    int wid = threadIdx.x >> 5, lid = threadIdx.x & 31;
    int r = blockIdx.x * 8 + wid;
    const float* row = e + (size_t)r * DIM;
    double s = 0.0;
#pragma unroll
    for (int i = 0; i < 8; ++i) {
        int c = i * 32 + lid;
        float v = row[c];
        g_eh[(size_t)r * DIM + c] = __float2bfloat16(v);
        s += (double)v * (double)v;
    }
#pragma unroll
    for (int o = 16; o; o >>= 1) s += __shfl_down_sync(0xffffffffu, s, o);
    if (lid == 0) g_B[r] = (float)s;
}

__global__ void k_normA() {
    int wid = threadIdx.x >> 5, lid = threadIdx.x & 31;
    int r = blockIdx.x * 8 + wid;
    const float* row = g_zf + (size_t)r * DIM;
    double s = 0.0;
#pragma unroll
    for (int i = 0; i < 8; ++i) {
        float v = row[i * 32 + lid];
        s += (double)v * (double)v;
    }
#pragma unroll
    for (int o = 16; o; o >>= 1) s += __shfl_down_sync(0xffffffffu, s, o);
    if (lid == 0) g_A[r] = (float)s;
}

// ---------------- coarse single-product bf16 GEMM ----------------
// grid (128, 128); 256 thr; warp grid 2x4 (wr=wid>>2, wc=wid&3); warp tile 64x32.
extern "C" __global__ void __launch_bounds__(256, 2)
k_coarse() {
    __shared__ __align__(16) char smem[2 * STAGE_B];
    uint32_t sb = smem_u32(smem);
    int tid = threadIdx.x;
    int l = tid & 31, wid = tid >> 5;
    int wr = wid >> 2, wc = wid & 3;
    int tok0 = blockIdx.x * TM, cb = blockIdx.y * TN;

    float acc[4][4][4];
#pragma unroll
    for (int mt = 0; mt < 4; ++mt)
#pragma unroll
        for (int nt = 0; nt < 4; ++nt)
#pragma unroll
            for (int f = 0; f < 4; ++f) acc[mt][nt][f] = 0.0f;

    int srow = tid >> 1, part = tid & 1;
    const uint4* srcZh = reinterpret_cast<const uint4*>(&g_zh[(size_t)(tok0 + srow) * DIM]);
    const uint4* srcEh = reinterpret_cast<const uint4*>(&g_eh[(size_t)(cb + srow) * DIM]);
    uint32_t stoff = (uint32_t)(srow * PITCH + part * 16);

    {
        uint4 a = srcZh[part], c = srcEh[part];
        *reinterpret_cast<uint4*>(smem + ZH_OFF + stoff) = a;
        *reinterpret_cast<uint4*>(smem + EH_OFF + stoff) = c;
    }
    __syncthreads();

    uint32_t a_lane = (uint32_t)((l & 15) * PITCH + (l >> 4) * 16);
    uint32_t b_lane = (uint32_t)(((l & 7) + ((l >> 4) << 3)) * PITCH + ((l >> 3) & 1) * 16);

    for (int ks = 0; ks < NSTEP; ++ks) {
        int cur = ks & 1;
        uint4 ra, rc;
        if (ks < NSTEP - 1) {
            int off = ((ks + 1) << 1) + part;
            ra = srcZh[off]; rc = srcEh[off];
        }
        uint32_t sbase = sb + (uint32_t)(cur * STAGE_B);

        uint32_t Bh[2][4];
#pragma unroll
        for (int pr = 0; pr < 2; ++pr) {
            uint32_t bd = sbase + EH_OFF + (uint32_t)((wc * 32 + pr * 16) * PITCH) + b_lane;
            LDSM4(Bh[pr], bd);
        }
#pragma unroll
        for (int mt = 0; mt < 4; ++mt) {
            uint32_t Ah[4];
            uint32_t ad = sbase + (uint32_t)((wr * 64 + mt * 16) * PITCH) + a_lane;
            LDSM4(Ah, ad);
#pragma unroll
            for (int pr = 0; pr < 2; ++pr)
#pragma unroll
                for (int h = 0; h < 2; ++h)
                    MMA_BF16(acc[mt][pr * 2 + h], Ah, Bh[pr][2 * h], Bh[pr][2 * h + 1]);
        }
        if (ks < NSTEP - 1) {
            __syncthreads();
            char* base = smem + (1 - cur) * STAGE_B;
            *reinterpret_cast<uint4*>(base + ZH_OFF + stoff) = ra;
            *reinterpret_cast<uint4*>(base + EH_OFF + stoff) = rc;
            __syncthreads();
        }
    }

    // epilogue: store s = B - 2*dot (fp16) + per-token coarse min
    __syncthreads();
    unsigned* scand = reinterpret_cast<unsigned*>(smem);
    if (tid < TM) scand[tid] = 0xFFFFFFFFu;
    __syncthreads();

#pragma unroll
    for (int mt = 0; mt < 4; ++mt)
#pragma unroll
        for (int fr = 0; fr < 2; ++fr) {
            int trow = wr * 64 + mt * 16 + (l >> 2) + fr * 8;
            float Aval = g_A[tok0 + trow];
            unsigned vmin = 0xFFFFFFFFu;
#pragma unroll
            for (int nt = 0; nt < 4; ++nt) {
                int code0 = cb + wc * 32 + nt * 8 + 2 * (l & 3);
                float dot0 = acc[mt][nt][fr * 2 + 0];
                float dot1 = acc[mt][nt][fr * 2 + 1];
                float B0 = g_B[code0], B1 = g_B[code0 + 1];
                float s0 = __fadd_rn(B0, -__fadd_rn(dot0, dot0));
                float s1 = __fadd_rn(B1, -__fadd_rn(dot1, dot1));
                __half2 hs = __floats2half2_rn(s0, s1);
                *reinterpret_cast<__half2*>(
                    &g_dmat[(size_t)(tok0 + trow) * NEMB + code0]) = hs;
                float d0 = __fadd_rn(__fadd_rn(Aval, B0), -__fadd_rn(dot0, dot0));
                float d1 = __fadd_rn(__fadd_rn(Aval, B1), -__fadd_rn(dot1, dot1));
                unsigned u0 = __float_as_uint(d0), u1 = __float_as_uint(d1);
                if (u0 < vmin) vmin = u0;
                if (u1 < vmin) vmin = u1;
            }
            unsigned o;
            o = __shfl_xor_sync(0xffffffffu, vmin, 1); if (o < vmin) vmin = o;
            o = __shfl_xor_sync(0xffffffffu, vmin, 2); if (o < vmin) vmin = o;
            if ((l & 3) == 0) atomicMin(&scand[trow], vmin);
        }
    __syncthreads();
    if (tid < TM) atomicMin(&g_cmin[tok0 + tid], scand[tid]);
}

// ---------------- candidate collection ----------------
// block per token: 256 threads x 64 codes each
__global__ void __launch_bounds__(256)
k_collect() {
    int t = blockIdx.x;
    float rhs = __fadd_rn(__fadd_rn(__uint_as_float(g_cmin[t]), MARGIN), -g_A[t]);
    const uint4* row = reinterpret_cast<const uint4*>(&g_dmat[(size_t)t * NEMB]);
    int c0 = threadIdx.x * 64;
#pragma unroll
    for (int i = 0; i < 8; ++i) {
        uint4 v = row[threadIdx.x * 8 + i];
        unsigned w[4] = {v.x, v.y, v.z, v.w};
#pragma unroll
        for (int q = 0; q < 4; ++q) {
            float2 f = __half22float2(*reinterpret_cast<__half2*>(&w[q]));
            int code = c0 + i * 8 + q * 2;
            if (f.x <= rhs) {
                int pos = atomicAdd(&g_ncand, 1);
                if (pos < NCAND_CAP) g_cand[pos] = ((unsigned)t << 14) | (unsigned)code;
            }
            if (f.y <= rhs) {
                int pos = atomicAdd(&g_ncand, 1);
                if (pos < NCAND_CAP) g_cand[pos] = ((unsigned)t << 14) | (unsigned)(code + 1);
            }
        }
    }
}

// ---------------- exact rescoring (warp per candidate) ----------------
__global__ void __launch_bounds__(256)
k_rescore() {
    int n = g_ncand;
    if (n > NCAND_CAP) n = NCAND_CAP;
    int l = threadIdx.x & 31;
    int wgid = (blockIdx.x * 256 + threadIdx.x) >> 5;
    int nwarps = gridDim.x * 8;
    for (int i = wgid; i < n; i += nwarps) {
        unsigned pc = g_cand[i];
        int t = (int)(pc >> 14), c = (int)(pc & 0x3FFFu);
        const float* zr = &g_zf[(size_t)t * DIM];
        const float* er = &g_eh[0] ? nullptr : nullptr;  // (unused)
        (void)er;
        const float* em = nullptr; (void)em;
        float dot = 0.0f;
        const float* e = (const float*)0; (void)e;
        // exact fp32 dot against original embedding (passed via g_emb ptr below)
        extern __device__ const float* g_embp;
        const float* erow = g_embp + (size_t)c * DIM;
#pragma unroll
        for (int k = 0; k < 8; ++k)
            dot = fmaf(zr[k * 32 + l], erow[k * 32 + l], dot);
#pragma unroll
        for (int o = 16; o; o >>= 1) dot += __shfl_xor_sync(0xffffffffu, dot, o);
        if (l == 0) {
            float d = __fadd_rn(__fadd_rn(g_A[t], g_B[c]),
                                -__fmul_rn(2.0f, dot));
            unsigned long long p =
                ((unsigned long long)__float_as_uint(d) << 32) | (unsigned)c;
            atomicMin(&g_best[t], p);
        }
    }
}
__device__ const float* g_embp;
__global__ void k_setemb(const float* e) { g_embp = e; }

// ---------------- outputs ----------------
__global__ void k_idx(float* __restrict__ out_idx, float* __restrict__ out_enc) {
    int n = blockIdx.x * blockDim.x + threadIdx.x;
    if (n >= NTOK) return;
    int idx = (int)(g_best[n] & 0xFFFFFFFFull);
    out_idx[n] = (float)idx;
    out_enc[(size_t)n * NEMB + idx] = 1.0f;
    atomicAdd(&g_cnt[idx], 1);
}

__global__ void k_finalize(const float* __restrict__ emb, float* __restrict__ out_zq) {
    __shared__ double red[1024];
    int g = blockIdx.x * 1024 + threadIdx.x;
    int b = g >> 18, c = (g >> 10) & 255, p = g & 1023;
    int n = b * 1024 + p;
    int idx = (int)(g_best[n] & 0xFFFFFFFFull);
    float zq = emb[(size_t)idx * DIM + c];
    float zp = g_zf[(size_t)n * DIM + c];
    float diff = __fsub_rn(zq, zp);
    out_zq[g] = __fadd_rn(zp, diff);
    red[threadIdx.x] = (double)__fmul_rn(diff, diff);
    __syncthreads();
    for (int s = 512; s > 0; s >>= 1) {
        if (threadIdx.x < s) red[threadIdx.x] += red[threadIdx.x + s];
        __syncthreads();
    }
    if (threadIdx.x == 0) g_part[blockIdx.x] = red[0];
}

__global__ void k_scalars(float* __restrict__ out_loss, float* __restrict__ out_perp) {
    __shared__ double red[1024];
    int t = threadIdx.x;
    double s = 0.0;
    for (int i = t; i < 4096; i += 1024) s += g_part[i];
    red[t] = s;
    __syncthreads();
    for (int w = 512; w > 0; w >>= 1) {
        if (t < w) red[t] += red[t + w];
        __syncthreads();
    }
    double total = red[0];
    __syncthreads();
    double ent = 0.0;
    for (int j = t; j < NEMB; j += 1024) {
        double e = (double)g_cnt[j] / (double)NTOK;
        ent += e * log(e + 1e-10);
    }
    red[t] = ent;
    __syncthreads();
    for (int w = 512; w > 0; w >>= 1) {
        if (t < w) red[t] += red[t + w];
        __syncthreads();
    }
    if (t == 0) {
        double m = total / (double)(NTOK * DIM);
        *out_loss = (float)(m + 0.25 * m);
        *out_perp = (float)exp(-red[0]);
    }
}

extern "C" void kernel_launch(void* const* d_in, const int* in_sizes, int n_in,
                              void* d_out, int out_size) {
    const float* z = (const float*)d_in[0];
    const float* emb = (const float*)d_in[1];
    float* out = (float*)d_out;

    const size_t ZQ_OFF = 0;
    const size_t LOSS_OFF = 4194304;
    const size_t PERP_OFF = 4194305;
    const size_t ENC_OFF = 4194306;
    const size_t IDX_OFF = ENC_OFF + (size_t)NTOK * NEMB;

    cudaMemsetAsync(out + ENC_OFF, 0, (size_t)NTOK * NEMB * sizeof(float));
    k_init<<<64, 256>>>();
    k_setemb<<<1, 1>>>(emb);
    {
        dim3 grid(32, 8, 16), blk(32, 32);
        k_prep_z<<<grid, blk>>>(z);
    }
    k_prep_e<<<2048, 256>>>(emb);
    k_normA<<<2048, 256>>>();
    {
        dim3 grid(NTOK / TM, NEMB / TN);
        k_coarse<<<grid, 256>>>();
    }
    k_collect<<<NTOK, 256>>>();
    k_rescore<<<256, 256>>>();
    k_idx<<<64, 256>>>(out + IDX_OFF, out + ENC_OFF);
    k_finalize<<<4096, 1024>>>(emb, out + ZQ_OFF);
    k_scalars<<<1, 1024>>>(out + LOSS_OFF, out + PERP_OFF);
    (void)in_sizes; (void)n_in; (void)out_size;
}